// round 1
// baseline (speedup 1.0000x reference)
#include <cuda_runtime.h>
#include <math.h>

#define H 1024
#define V 50000
#define MAXLEN 35

// -------- scratch (no allocations allowed) --------
__device__ float g_u[2 * H];      // [embedded ; attn_applied]
__device__ float g_comb[H];       // relu(combine)
__device__ float g_xg[3 * H];     // W_ih @ comb + b_ih
__device__ float g_hg[3 * H];     // W_hh @ h + b_hh
__device__ float g_hnew[H];       // new hidden
__device__ float g_logits[V];     // pre-softmax logits
__device__ float g_red[2];        // {max, log(sum exp)}

__device__ __forceinline__ float warp_sum(float v) {
    #pragma unroll
    for (int o = 16; o > 0; o >>= 1) v += __shfl_down_sync(0xffffffffu, v, o);
    return v;
}

// K1: embedding gather + additive attention + softmax + attn_applied (1 block, 1024 thr)
__global__ void k1_attn(const int* __restrict__ x, const float* __restrict__ h,
                        const float* __restrict__ enc, const float* __restrict__ emb,
                        const float* __restrict__ Wa, const float* __restrict__ ba,
                        float* __restrict__ out) {
    __shared__ float s_in[2 * H];
    __shared__ float s_w[MAXLEN];
    const int tid = threadIdx.x;
    const long row = (long)x[0];

    for (int i = tid; i < H; i += 1024) {
        float e = emb[row * H + i];
        s_in[i] = e;
        g_u[i]  = e;                 // embedded half of combine input
    }
    for (int i = tid; i < H; i += 1024) s_in[H + i] = h[i];
    __syncthreads();

    const int w = tid >> 5, lane = tid & 31;
    for (int m = w; m < MAXLEN; m += 32) {
        const float* Wr = Wa + (long)m * (2 * H);
        float acc = 0.f;
        for (int k = lane; k < 2 * H; k += 32) acc += Wr[k] * s_in[k];
        acc = warp_sum(acc);
        if (lane == 0) s_w[m] = acc + ba[m];
    }
    __syncthreads();

    if (tid == 0) {
        float mx = -1e30f;
        for (int m = 0; m < MAXLEN; m++) mx = fmaxf(mx, s_w[m]);
        float s = 0.f;
        for (int m = 0; m < MAXLEN; m++) { float e = expf(s_w[m] - mx); s_w[m] = e; s += e; }
        float inv = 1.f / s;
        for (int m = 0; m < MAXLEN; m++) s_w[m] *= inv;
    }
    __syncthreads();

    if (tid < MAXLEN) out[V + H + tid] = s_w[tid];

    for (int i = tid; i < H; i += 1024) {
        float acc = 0.f;
        #pragma unroll
        for (int m = 0; m < MAXLEN; m++) acc += s_w[m] * enc[m * H + i];
        g_u[H + i] = acc;            // attn_applied half
    }
}

// K2: comb = relu(W_comb @ u + b_comb)   rows=H, cols=2H, warp per row
__global__ void k2_comb(const float* __restrict__ Wc, const float* __restrict__ bc) {
    __shared__ float4 s_u[(2 * H) / 4];
    const int tid = threadIdx.x;          // 256
    for (int i = tid; i < (2 * H) / 4; i += 256)
        s_u[i] = reinterpret_cast<const float4*>(g_u)[i];
    __syncthreads();

    const int warp = tid >> 5, lane = tid & 31;
    const int row = blockIdx.x * 8 + warp;
    if (row >= H) return;
    const float4* Wr = reinterpret_cast<const float4*>(Wc + (long)row * (2 * H));
    float acc = 0.f;
    #pragma unroll
    for (int c = lane; c < (2 * H) / 4; c += 32) {
        float4 wv = Wr[c], uv = s_u[c];
        acc += wv.x * uv.x + wv.y * uv.y + wv.z * uv.z + wv.w * uv.w;
    }
    acc = warp_sum(acc);
    if (lane == 0) g_comb[row] = fmaxf(acc + bc[row], 0.f);
}

// K3: xg = W_ih @ comb + b_ih ; hg = W_hh @ h + b_hh   rows=3H, warp per row (both dots)
__global__ void k3_gates(const float* __restrict__ Wih, const float* __restrict__ bih,
                         const float* __restrict__ Whh, const float* __restrict__ bhh,
                         const float* __restrict__ h) {
    __shared__ float4 s_c[H / 4];
    __shared__ float4 s_h[H / 4];
    const int tid = threadIdx.x;          // 256
    for (int i = tid; i < H / 4; i += 256) {
        s_c[i] = reinterpret_cast<const float4*>(g_comb)[i];
        s_h[i] = reinterpret_cast<const float4*>(h)[i];
    }
    __syncthreads();

    const int warp = tid >> 5, lane = tid & 31;
    const int row = blockIdx.x * 8 + warp;
    if (row >= 3 * H) return;
    const float4* W1 = reinterpret_cast<const float4*>(Wih + (long)row * H);
    const float4* W2 = reinterpret_cast<const float4*>(Whh + (long)row * H);
    float a1 = 0.f, a2 = 0.f;
    #pragma unroll
    for (int c = lane; c < H / 4; c += 32) {
        float4 w1 = W1[c], w2 = W2[c], cv = s_c[c], hv = s_h[c];
        a1 += w1.x * cv.x + w1.y * cv.y + w1.z * cv.z + w1.w * cv.w;
        a2 += w2.x * hv.x + w2.y * hv.y + w2.z * hv.z + w2.w * hv.w;
    }
    a1 = warp_sum(a1);
    a2 = warp_sum(a2);
    if (lane == 0) { g_xg[row] = a1 + bih[row]; g_hg[row] = a2 + bhh[row]; }
}

// K4: GRU elementwise update (1 block, H threads)
__global__ void k4_gru(const float* __restrict__ h, float* __restrict__ out) {
    const int j = threadIdx.x;
    float r = 1.f / (1.f + expf(-(g_xg[j] + g_hg[j])));
    float z = 1.f / (1.f + expf(-(g_xg[H + j] + g_hg[H + j])));
    float n = tanhf(g_xg[2 * H + j] + r * g_hg[2 * H + j]);
    float hn = (1.f - z) * n + z * h[j];
    g_hnew[j] = hn;
    out[V + j] = hn;
}

// K5: logits = W_out @ h_new + b_out   rows=V, warp per row  (the 200MB streamer)
__global__ void k5_logits(const float* __restrict__ Wo, const float* __restrict__ bo) {
    __shared__ float4 s_h[H / 4];
    const int tid = threadIdx.x;          // 256
    for (int i = tid; i < H / 4; i += 256)
        s_h[i] = reinterpret_cast<const float4*>(g_hnew)[i];
    __syncthreads();

    const int warp = tid >> 5, lane = tid & 31;
    const int row = blockIdx.x * 8 + warp;
    if (row >= V) return;
    const float4* Wr = reinterpret_cast<const float4*>(Wo + (long)row * H);
    float acc = 0.f;
    #pragma unroll 8
    for (int c = lane; c < H / 4; c += 32) {
        float4 w = Wr[c], hv = s_h[c];
        acc += w.x * hv.x + w.y * hv.y + w.z * hv.z + w.w * hv.w;
    }
    acc = warp_sum(acc);
    if (lane == 0) g_logits[row] = acc + bo[row];
}

// K6: deterministic max + logsumexp over V (1 block, 1024 thr)
__global__ void k6_red() {
    __shared__ float sm[32];
    __shared__ float ss[32];
    const int tid = threadIdx.x, lane = tid & 31, w = tid >> 5;

    float mx = -1e30f;
    for (int v = tid; v < V; v += 1024) mx = fmaxf(mx, g_logits[v]);
    #pragma unroll
    for (int o = 16; o > 0; o >>= 1) mx = fmaxf(mx, __shfl_down_sync(0xffffffffu, mx, o));
    if (lane == 0) sm[w] = mx;
    __syncthreads();
    if (tid < 32) {
        float v = sm[tid];
        #pragma unroll
        for (int o = 16; o > 0; o >>= 1) v = fmaxf(v, __shfl_down_sync(0xffffffffu, v, o));
        if (tid == 0) sm[0] = v;
    }
    __syncthreads();
    const float M = sm[0];

    float s = 0.f;
    for (int v = tid; v < V; v += 1024) s += expf(g_logits[v] - M);
    s = warp_sum(s);
    if (lane == 0) ss[w] = s;
    __syncthreads();
    if (tid < 32) {
        float v = ss[tid];
        v = warp_sum(v);
        if (tid == 0) { g_red[0] = M; g_red[1] = logf(v); }
    }
}

// K7: logp = logits - max - log(sum)
__global__ void k7_out(float* __restrict__ out) {
    const int v = blockIdx.x * blockDim.x + threadIdx.x;
    if (v < V) out[v] = g_logits[v] - g_red[0] - g_red[1];
}

extern "C" void kernel_launch(void* const* d_in, const int* in_sizes, int n_in,
                              void* d_out, int out_size) {
    const int*   x   = (const int*)  d_in[0];
    const float* h   = (const float*)d_in[1];   // h_state (1,1,H)
    // d_in[2] = encoder_output (unused by reference)
    const float* enc = (const float*)d_in[3];   // encoder_outputs (MAXLEN,H)
    const float* emb = (const float*)d_in[4];
    const float* Wa  = (const float*)d_in[5];
    const float* ba  = (const float*)d_in[6];
    const float* Wc  = (const float*)d_in[7];
    const float* bc  = (const float*)d_in[8];
    const float* Wih = (const float*)d_in[9];
    const float* bih = (const float*)d_in[10];
    const float* Whh = (const float*)d_in[11];
    const float* bhh = (const float*)d_in[12];
    const float* Wo  = (const float*)d_in[13];
    const float* bo  = (const float*)d_in[14];
    float* out = (float*)d_out;

    k1_attn<<<1, 1024>>>(x, h, enc, emb, Wa, ba, out);
    k2_comb<<<H / 8, 256>>>(Wc, bc);
    k3_gates<<<(3 * H) / 8, 256>>>(Wih, bih, Whh, bhh, h);
    k4_gru<<<1, H>>>(h, out);
    k5_logits<<<(V + 7) / 8, 256>>>(Wo, bo);
    k6_red<<<1, 1024>>>();
    k7_out<<<(V + 255) / 256, 256>>>(out);
}

// round 3
// speedup vs baseline: 1.0306x; 1.0306x over previous
#include <cuda_runtime.h>
#include <math.h>

#define H 1024
#define V 50000
#define MAXLEN 35
#define NB 148
#define NT 512
#define NWARP (NT / 32)        // 16 warps per block
#define GWARPS (NB * NWARP)    // 2368 warps total

// -------- device scratch (zero-initialized at module load; no allocs) --------
__device__ float g_u[2 * H];       // [embedded ; attn_applied]
__device__ float g_hg[3 * H];      // W_hh @ h + b_hh
__device__ float g_comb[H];        // relu(W_comb @ u + b_comb)
__device__ float g_hnew[H];        // updated hidden state
__device__ float g_logits[V];      // pre-softmax logits
__device__ float g_bm[NB];         // per-block online max
__device__ float g_bs[NB];         // per-block online scaled sum
__device__ float g_red[1];         // M + log(S)
__device__ unsigned g_count[8];    // barrier arrive counters (self-resetting)
__device__ unsigned g_gen[8];      // barrier generations (monotonic across replays)

__device__ __forceinline__ float warp_sum(float v) {
    #pragma unroll
    for (int o = 16; o > 0; o >>= 1) v += __shfl_down_sync(0xffffffffu, v, o);
    return v;
}

// Grid-wide barrier: generation counters are monotonic across graph replays, so
// no reset hazard; arrive counter is reset by the last arriver before release.
__device__ __forceinline__ void gsync(int p) {
    __threadfence();            // release all this thread's global writes (+ L1 inval)
    __syncthreads();
    if (threadIdx.x == 0) {
        volatile unsigned* genp = &g_gen[p];
        unsigned gen = *genp;
        unsigned old = atomicAdd(&g_count[p], 1u);
        if (old == NB - 1) {
            g_count[p] = 0;
            __threadfence();
            atomicAdd(&g_gen[p], 1u);   // release
        } else {
            while (*genp == gen) { __nanosleep(64); }
        }
    }
    __syncthreads();
}

__global__ void __launch_bounds__(NT, 1)
fused_decoder(const int* __restrict__ x, const float* __restrict__ h,
              const float* __restrict__ enc, const float* __restrict__ emb,
              const float* __restrict__ Wa, const float* __restrict__ ba,
              const float* __restrict__ Wc, const float* __restrict__ bc,
              const float* __restrict__ Wih, const float* __restrict__ bih,
              const float* __restrict__ Whh, const float* __restrict__ bhh,
              const float* __restrict__ Wo, const float* __restrict__ bo,
              float* __restrict__ out) {
    __shared__ float sbuf[2 * H];       // phase-dependent vector cache
    __shared__ float s_w[64];           // attention scores / weights (block 0)
    __shared__ float s_m[NWARP], s_s[NWARP];

    const int tid = threadIdx.x;
    const int wid = tid >> 5;
    const int lane = tid & 31;
    const int b = blockIdx.x;

    // ===== P0: block 0 -> embedding + attention;  blocks 1..147 -> hg = W_hh@h + b_hh
    if (b == 0) {
        const long row = (long)x[0];
        for (int i = tid; i < H; i += NT) {
            float e = emb[row * H + i];
            sbuf[i] = e;
            g_u[i]  = e;
        }
        for (int i = tid; i < H; i += NT) sbuf[H + i] = h[i];
        __syncthreads();

        for (int m = wid; m < MAXLEN; m += NWARP) {
            const float* Wr = Wa + (long)m * (2 * H);
            float acc = 0.f;
            for (int k = lane; k < 2 * H; k += 32) acc += Wr[k] * sbuf[k];
            acc = warp_sum(acc);
            if (lane == 0) s_w[m] = acc + ba[m];
        }
        __syncthreads();

        if (tid == 0) {
            float mx = -1e30f;
            for (int m = 0; m < MAXLEN; m++) mx = fmaxf(mx, s_w[m]);
            float s = 0.f;
            for (int m = 0; m < MAXLEN; m++) { float e = expf(s_w[m] - mx); s_w[m] = e; s += e; }
            float inv = 1.f / s;
            for (int m = 0; m < MAXLEN; m++) s_w[m] *= inv;
        }
        __syncthreads();

        if (tid < MAXLEN) out[V + H + tid] = s_w[tid];

        for (int i = tid; i < H; i += NT) {
            float acc = 0.f;
            #pragma unroll
            for (int m = 0; m < MAXLEN; m++) acc += s_w[m] * enc[m * H + i];
            g_u[H + i] = acc;
        }
    } else {
        const int gw = (b - 1) * NWARP + wid;           // 0..2351
        const float4* hv = reinterpret_cast<const float4*>(h);
        for (int r = gw; r < 3 * H; r += (NB - 1) * NWARP) {
            const float4* Wr = reinterpret_cast<const float4*>(Whh + (long)r * H);
            float acc = 0.f;
            #pragma unroll 8
            for (int c = lane; c < H / 4; c += 32) {
                float4 w = Wr[c], v = hv[c];
                acc += w.x * v.x + w.y * v.y + w.z * v.z + w.w * v.w;
            }
            acc = warp_sum(acc);
            if (lane == 0) g_hg[r] = acc + bhh[r];
        }
    }
    gsync(0);

    // ===== P1: comb = relu(W_comb @ u + b_comb), one row per warp (rows 0..H-1)
    for (int i = tid; i < 2 * H; i += NT) sbuf[i] = g_u[i];
    __syncthreads();
    {
        const int r = b + NB * wid;                      // unique in 0..2367
        if (r < H) {
            const float4* Wr = reinterpret_cast<const float4*>(Wc + (long)r * (2 * H));
            const float4* uv = reinterpret_cast<const float4*>(sbuf);
            float acc = 0.f;
            #pragma unroll 8
            for (int c = lane; c < (2 * H) / 4; c += 32) {
                float4 w = Wr[c], v = uv[c];
                acc += w.x * v.x + w.y * v.y + w.z * v.z + w.w * v.w;
            }
            acc = warp_sum(acc);
            if (lane == 0) g_comb[r] = fmaxf(acc + bc[r], 0.f);
        }
    }
    gsync(1);

    // ===== P2: GRU gates + elementwise update fused; warp owns one j
    __syncthreads();
    for (int i = tid; i < H; i += NT) sbuf[i] = g_comb[i];
    __syncthreads();
    {
        const int j = b + NB * wid;
        if (j < H) {
            const float4* W0 = reinterpret_cast<const float4*>(Wih + (long)j * H);
            const float4* W1 = reinterpret_cast<const float4*>(Wih + (long)(H + j) * H);
            const float4* W2 = reinterpret_cast<const float4*>(Wih + (long)(2 * H + j) * H);
            const float4* cv = reinterpret_cast<const float4*>(sbuf);
            float a0 = 0.f, a1 = 0.f, a2 = 0.f;
            #pragma unroll 4
            for (int c = lane; c < H / 4; c += 32) {
                float4 v = cv[c];
                float4 w0 = W0[c], w1 = W1[c], w2 = W2[c];
                a0 += w0.x * v.x + w0.y * v.y + w0.z * v.z + w0.w * v.w;
                a1 += w1.x * v.x + w1.y * v.y + w1.z * v.z + w1.w * v.w;
                a2 += w2.x * v.x + w2.y * v.y + w2.z * v.z + w2.w * v.w;
            }
            a0 = warp_sum(a0); a1 = warp_sum(a1); a2 = warp_sum(a2);
            if (lane == 0) {
                float xr = a0 + bih[j];
                float xz = a1 + bih[H + j];
                float xn = a2 + bih[2 * H + j];
                float rr = 1.f / (1.f + expf(-(xr + g_hg[j])));
                float zz = 1.f / (1.f + expf(-(xz + g_hg[H + j])));
                float nn = tanhf(xn + rr * g_hg[2 * H + j]);
                float hv = (1.f - zz) * nn + zz * h[j];
                g_hnew[j] = hv;
                out[V + j] = hv;
            }
        }
    }
    gsync(2);

    // ===== P3: logits = W_out @ hnew + b_out, with online logsumexp per warp
    __syncthreads();
    for (int i = tid; i < H; i += NT) sbuf[i] = g_hnew[i];
    __syncthreads();
    {
        const int gw = b * NWARP + wid;                  // 0..2367
        const float4* hv = reinterpret_cast<const float4*>(sbuf);
        float mx = -1e30f, sm = 0.f;                     // lane-0 carries the state
        for (int r = gw; r < V; r += GWARPS) {
            const float4* Wr = reinterpret_cast<const float4*>(Wo + (long)r * H);
            float acc = 0.f;
            #pragma unroll 8
            for (int c = lane; c < H / 4; c += 32) {
                float4 w = Wr[c], v = hv[c];
                acc += w.x * v.x + w.y * v.y + w.z * v.z + w.w * v.w;
            }
            acc = warp_sum(acc);
            if (lane == 0) {
                float lg = acc + bo[r];
                g_logits[r] = lg;
                float nm = fmaxf(mx, lg);
                sm = sm * expf(mx - nm) + expf(lg - nm);
                mx = nm;
            }
        }
        if (lane == 0) { s_m[wid] = mx; s_s[wid] = sm; }
        __syncthreads();
        if (tid == 0) {
            float M = -1e30f, S = 0.f;
            #pragma unroll
            for (int w = 0; w < NWARP; w++) {
                float m2 = s_m[w], s2 = s_s[w];
                float nm = fmaxf(M, m2);
                S = S * expf(M - nm) + s2 * expf(m2 - nm);
                M = nm;
            }
            g_bm[b] = M; g_bs[b] = S;
        }
    }
    gsync(3);

    // ===== P4: block 0 warp 0 reduces the 148 (m,s) pairs -> M + log(S)
    if (b == 0 && wid == 0) {
        float M = -1e30f, S = 0.f;
        for (int i = lane; i < NB; i += 32) {
            float m2 = g_bm[i], s2 = g_bs[i];
            float nm = fmaxf(M, m2);
            S = S * expf(M - nm) + s2 * expf(m2 - nm);
            M = nm;
        }
        #pragma unroll
        for (int o = 16; o > 0; o >>= 1) {
            float m2 = __shfl_down_sync(0xffffffffu, M, o);
            float s2 = __shfl_down_sync(0xffffffffu, S, o);
            float nm = fmaxf(M, m2);
            S = S * expf(M - nm) + s2 * expf(m2 - nm);
            M = nm;
        }
        if (lane == 0) g_red[0] = M + logf(S);
    }
    gsync(4);

    // ===== P5: logp = logits - (M + log S)
    {
        const float off = g_red[0];
        for (int v = b * NT + tid; v < V; v += NB * NT) out[v] = g_logits[v] - off;
    }
}

extern "C" void kernel_launch(void* const* d_in, const int* in_sizes, int n_in,
                              void* d_out, int out_size) {
    const int*   x   = (const int*)  d_in[0];
    const float* h   = (const float*)d_in[1];   // h_state (1,1,H)
    // d_in[2] = encoder_output (unused by reference)
    const float* enc = (const float*)d_in[3];   // encoder_outputs (MAXLEN,H)
    const float* emb = (const float*)d_in[4];
    const float* Wa  = (const float*)d_in[5];
    const float* ba  = (const float*)d_in[6];
    const float* Wc  = (const float*)d_in[7];
    const float* bc  = (const float*)d_in[8];
    const float* Wih = (const float*)d_in[9];
    const float* bih = (const float*)d_in[10];
    const float* Whh = (const float*)d_in[11];
    const float* bhh = (const float*)d_in[12];
    const float* Wo  = (const float*)d_in[13];
    const float* bo  = (const float*)d_in[14];
    float* out = (float*)d_out;

    fused_decoder<<<NB, NT>>>(x, h, enc, emb, Wa, ba, Wc, bc,
                              Wih, bih, Whh, bhh, Wo, bo, out);
}